// round 2
// baseline (speedup 1.0000x reference)
#include <cuda_runtime.h>

#define TILE_B   16
#define THREADS  256
#define NB       8192
#define NIO      64

// Precomputed per-(o,i) coefficient tables, laid out [i][o] for coalesced
// per-o lane reads.  A = {c1', b2', b3', b4}, B = {c5..c8} (gamma/64 folded).
__device__ float4 g_tabA[NIO * NIO];
__device__ float4 g_tabB[NIO * NIO];

__device__ __forceinline__ float ex2f_(float x) {
    float y; asm("ex2.approx.ftz.f32 %0, %1;" : "=f"(y) : "f"(x)); return y;
}
__device__ __forceinline__ float lg2f_(float x) {
    float y; asm("lg2.approx.ftz.f32 %0, %1;" : "=f"(y) : "f"(x)); return y;
}

// ---------------------------------------------------------------------------
// Setup: evaluate the 8 cubic splines at w_norm for every (o,i) pair and fold
// all constant factors so the main loop is pure EX2/LG2 + FFMA.
// ---------------------------------------------------------------------------
__global__ void setup_kernel(const float* __restrict__ raw_gamma,
                             const float* __restrict__ w,
                             const float* __restrict__ breaks,
                             const float* __restrict__ coefs,
                             const float* __restrict__ mu_p,
                             const float* __restrict__ sig_p)
{
    int tid = blockIdx.x * blockDim.x + threadIdx.x;
    if (tid >= NIO * NIO) return;
    int o = tid >> 6;
    int i = tid & 63;

    float mu  = *mu_p;
    float sig = *sig_p;
    float wv  = w[tid];                       // w[o][i]
    float wc  = fminf(fmaxf(wv, -5.5f), 37.9f);
    float wn  = (wc - mu) / sig;

    float b[8];
#pragma unroll
    for (int s = 0; s < 8; s++) {
        const float* br = breaks + s * 20;
        float blo = br[0];
        float bhi = br[19] - 1e-6f;
        float wl  = fminf(fmaxf(wn, blo), bhi);
        int cnt = 0;
#pragma unroll
        for (int k = 0; k < 20; k++) cnt += (br[k] < wl) ? 1 : 0;
        int idx = cnt - 1;
        idx = max(idx, 0);
        idx = min(idx, 18);
        const float* a = coefs + (s * 19 + idx) * 4;
        float t = wl - br[idx];
        b[s] = ((a[0] * t + a[1]) * t + a[2]) * t + a[3];
    }

    float rg = raw_gamma[tid];
    float g  = (rg > 20.f) ? rg : log1pf(expf(rg));   // softplus
    float scale = g * (1.0f / 64.0f);

    const float LN2   = 0.6931471805599453f;
    const float LOG2E = 1.4426950408889634f;

    float4 A, Bq;
    A.x = b[0] * scale * LN2;   // c1'
    A.y = b[1] * LN2;           // b2'
    A.z = b[2] * LOG2E;         // b3'
    A.w = b[3];                 // b4
    Bq.x = b[4] * scale;
    Bq.y = b[5] * scale;
    Bq.z = b[6] * scale;
    Bq.w = b[7] * scale;

    int p = i * NIO + o;        // [i][o] layout
    g_tabA[p] = A;
    g_tabB[p] = Bq;
}

// ---------------------------------------------------------------------------
// Main kernel.  Block = 256 threads = 8 warps, TILE_B=16 rows.
// Phase 2 compacts each row's active (x>0) indices into a packed uchar list
// (padded to even count with an inactive index; the +1e-30 guard makes the
// pad's contribution exactly ~0).  Phase 3 runs a counted loop, 2 independent
// MUFU chains per iteration, 2 accumulators.
// ---------------------------------------------------------------------------
__global__ __launch_bounds__(THREADS, 4)
void main_kernel(const float* __restrict__ x, float* __restrict__ out)
{
    __shared__ float         xs[TILE_B * 64];
    __shared__ unsigned char ids[TILE_B * 64];
    __shared__ int           cnts[TILE_B];

    const int tid  = threadIdx.x;
    const long base = (long)blockIdx.x * TILE_B * 64;

    // Phase 1: load x tile + relu (coalesced)
#pragma unroll
    for (int idx = tid; idx < TILE_B * 64; idx += THREADS)
        xs[idx] = fmaxf(x[base + idx], 0.f);
    __syncthreads();

    const int lane = tid & 31;
    const int wp   = tid >> 5;
    const unsigned lmask_lt = (lane == 0) ? 0u : (0xffffffffu >> (32 - lane));

    // Phase 2: compact active indices.  Warp wp handles rows 2wp, 2wp+1.
#pragma unroll
    for (int rr = 0; rr < 2; rr++) {
        int r = wp * 2 + rr;
        float v0 = xs[r * 64 + lane];
        float v1 = xs[r * 64 + 32 + lane];
        unsigned b0 = __ballot_sync(0xffffffffu, v0 > 0.f);
        unsigned b1 = __ballot_sync(0xffffffffu, v1 > 0.f);
        int c0 = __popc(b0);
        if (v0 > 0.f) ids[r * 64 + __popc(b0 & lmask_lt)] = (unsigned char)lane;
        if (v1 > 0.f) ids[r * 64 + c0 + __popc(b1 & lmask_lt)] = (unsigned char)(lane + 32);
        if (lane == 0) {
            int cnt = c0 + __popc(b1);
            if (cnt & 1) {
                // pad with an inactive index (x == 0 there -> contributes ~0)
                unsigned n0 = ~b0;
                int p = n0 ? (__ffs(n0) - 1) : (32 + __ffs(~b1) - 1);
                ids[r * 64 + cnt] = (unsigned char)p;
                cnt++;
            }
            cnts[r] = cnt;
        }
    }
    __syncthreads();

    // Phase 3: main loop.  warp -> o-half (wp&1), row stride 4 (wp>>1).
    const int o = lane + (wp & 1) * 32;

    for (int r = wp >> 1; r < TILE_B; r += 4) {
        const float* xrow = xs + r * 64;
        const unsigned char* idl = ids + r * 64;
        const int cnt = cnts[r];
        float acc0 = 0.f, acc1 = 0.f;

        for (int k = 0; k < cnt; k += 2) {
            unsigned short pr = *(const unsigned short*)(idl + k);
            int i0 = pr & 0xff;
            int i1 = pr >> 8;

            float xv0 = xrow[i0];
            float xv1 = xrow[i1];
            float4 A0  = __ldg(&g_tabA[i0 * NIO + o]);
            float4 A1  = __ldg(&g_tabA[i1 * NIO + o]);
            float4 B0  = __ldg(&g_tabB[i0 * NIO + o]);
            float4 B1  = __ldg(&g_tabB[i1 * NIO + o]);

            // chain 0
            float e0  = ex2f_(A0.z * xv0) - 1.f + 1e-30f;
            float p0  = ex2f_(A0.w * lg2f_(e0));
            float l10 = lg2f_(1.f + p0);
            float l20 = lg2f_(fmaf(A0.y, l10, 1.f));
            acc0 = fmaf(A0.x, l20, acc0);
            float x20 = xv0 * xv0;
            float pA0 = fmaf(B0.z, x20, B0.x);
            float pB0 = fmaf(B0.w, x20, B0.y);
            acc0 = fmaf(fmaf(pB0, xv0, pA0), xv0, acc0);

            // chain 1 (independent)
            float e1  = ex2f_(A1.z * xv1) - 1.f + 1e-30f;
            float p1  = ex2f_(A1.w * lg2f_(e1));
            float l11 = lg2f_(1.f + p1);
            float l21 = lg2f_(fmaf(A1.y, l11, 1.f));
            acc1 = fmaf(A1.x, l21, acc1);
            float x21 = xv1 * xv1;
            float pA1 = fmaf(B1.z, x21, B1.x);
            float pB1 = fmaf(B1.w, x21, B1.y);
            acc1 = fmaf(fmaf(pB1, xv1, pA1), xv1, acc1);
        }

        out[((long)blockIdx.x * TILE_B + r) * 64 + o] = acc0 + acc1;
    }
}

// ---------------------------------------------------------------------------
extern "C" void kernel_launch(void* const* d_in, const int* in_sizes, int n_in,
                              void* d_out, int out_size)
{
    const float* x   = (const float*)d_in[0];
    const float* rg  = (const float*)d_in[1];
    const float* w   = (const float*)d_in[2];
    const float* br  = (const float*)d_in[3];
    const float* cf  = (const float*)d_in[4];
    const float* mu  = (const float*)d_in[5];
    const float* sg  = (const float*)d_in[6];
    float* out = (float*)d_out;

    setup_kernel<<<(NIO * NIO + 255) / 256, 256>>>(rg, w, br, cf, mu, sg);
    main_kernel<<<NB / TILE_B, THREADS>>>(x, out);
}

// round 3
// speedup vs baseline: 1.5750x; 1.5750x over previous
#include <cuda_runtime.h>

#define TILE_B   4
#define THREADS  256
#define NB       8192
#define NIO      64

// Precomputed per-(o,i) coefficient tables, laid out [i][o] for coalesced
// per-o lane reads.  A = {c1', b2', b3', b4}, B = {c5..c8} (gamma/64 folded).
__device__ float4 g_tabA[NIO * NIO];
__device__ float4 g_tabB[NIO * NIO];

__device__ __forceinline__ float ex2f_(float x) {
    float y; asm("ex2.approx.ftz.f32 %0, %1;" : "=f"(y) : "f"(x)); return y;
}
__device__ __forceinline__ float lg2f_(float x) {
    float y; asm("lg2.approx.ftz.f32 %0, %1;" : "=f"(y) : "f"(x)); return y;
}

// ---------------------------------------------------------------------------
// Setup: evaluate the 8 cubic splines at w_norm for every (o,i) pair and fold
// all constant factors so the main loop is pure EX2/LG2 + FFMA.
// ---------------------------------------------------------------------------
__global__ void setup_kernel(const float* __restrict__ raw_gamma,
                             const float* __restrict__ w,
                             const float* __restrict__ breaks,
                             const float* __restrict__ coefs,
                             const float* __restrict__ mu_p,
                             const float* __restrict__ sig_p)
{
    int tid = blockIdx.x * blockDim.x + threadIdx.x;
    if (tid >= NIO * NIO) return;
    int o = tid >> 6;
    int i = tid & 63;

    float mu  = *mu_p;
    float sig = *sig_p;
    float wv  = w[tid];                       // w[o][i]
    float wc  = fminf(fmaxf(wv, -5.5f), 37.9f);
    float wn  = (wc - mu) / sig;

    float b[8];
#pragma unroll
    for (int s = 0; s < 8; s++) {
        const float* br = breaks + s * 20;
        float blo = br[0];
        float bhi = br[19] - 1e-6f;
        float wl  = fminf(fmaxf(wn, blo), bhi);
        int cnt = 0;
#pragma unroll
        for (int k = 0; k < 20; k++) cnt += (br[k] < wl) ? 1 : 0;
        int idx = cnt - 1;
        idx = max(idx, 0);
        idx = min(idx, 18);
        const float* a = coefs + (s * 19 + idx) * 4;
        float t = wl - br[idx];
        b[s] = ((a[0] * t + a[1]) * t + a[2]) * t + a[3];
    }

    float rg = raw_gamma[tid];
    float g  = (rg > 20.f) ? rg : log1pf(expf(rg));   // softplus
    float scale = g * (1.0f / 64.0f);

    const float LN2   = 0.6931471805599453f;
    const float LOG2E = 1.4426950408889634f;

    float4 A, Bq;
    A.x = b[0] * scale * LN2;   // c1'
    A.y = b[1] * LN2;           // b2'
    A.z = b[2] * LOG2E;         // b3'
    A.w = b[3];                 // b4
    Bq.x = b[4] * scale;
    Bq.y = b[5] * scale;
    Bq.z = b[6] * scale;
    Bq.w = b[7] * scale;

    int p = i * NIO + o;        // [i][o] layout
    g_tabA[p] = A;
    g_tabB[p] = Bq;
}

// ---------------------------------------------------------------------------
// Main kernel.  Block = 256 threads = 8 warps, TILE_B=4 rows, grid=2048.
// Warp wp -> row (wp>>1), o-half (wp&1).  Each warp builds its own 2x32-bit
// activity masks via ballot and drains lo/hi TOGETHER: two independent MUFU
// chains per loop iteration with zero compaction overhead.
// ---------------------------------------------------------------------------
__global__ __launch_bounds__(THREADS)
void main_kernel(const float* __restrict__ x, float* __restrict__ out)
{
    __shared__ float xs[TILE_B * 64];

    const int tid   = threadIdx.x;
    const long base = (long)blockIdx.x * (TILE_B * 64);

    // Phase 1: load x tile + relu (one element per thread, coalesced)
    xs[tid] = fmaxf(x[base + tid], 0.f);
    __syncthreads();

    const int lane = tid & 31;
    const int wp   = tid >> 5;
    const int r    = wp >> 1;
    const int o    = lane + (wp & 1) * 32;

    const float* xrow = xs + r * 64;
    float v0 = xrow[lane];
    float v1 = xrow[lane + 32];
    unsigned lo = __ballot_sync(0xffffffffu, v0 > 0.f);
    unsigned hi = __ballot_sync(0xffffffffu, v1 > 0.f);

    const float4* tA = g_tabA + o;
    const float4* tB = g_tabB + o;

    float acc0 = 0.f, acc1 = 0.f;

#define STEP(ACC, II)                                                     \
    {                                                                     \
        int ii = (II);                                                    \
        float xv = xrow[ii];              /* uniform broadcast LDS */     \
        float4 A  = __ldg(tA + ii * NIO);                                 \
        float4 Bq = __ldg(tB + ii * NIO);                                 \
        float e  = ex2f_(A.z * xv) - 1.f;                                 \
        float p  = ex2f_(A.w * lg2f_(e));                                 \
        float l1 = lg2f_(1.f + p);                                        \
        float l2 = lg2f_(fmaf(A.y, l1, 1.f));                             \
        ACC = fmaf(A.x, l2, ACC);                                         \
        float x2 = xv * xv;                                               \
        float pA = fmaf(Bq.z, x2, Bq.x);  /* c5 + c7 x^2 */               \
        float pB = fmaf(Bq.w, x2, Bq.y);  /* c6 + c8 x^2 */               \
        ACC = fmaf(fmaf(pB, xv, pA), xv, ACC);                            \
    }

    // Drain both masks together: 2 independent chains per iteration.
    while (lo && hi) {
        int i0 = __ffs(lo) - 1;      lo &= lo - 1;
        int i1 = __ffs(hi) + 31;     hi &= hi - 1;
        STEP(acc0, i0);
        STEP(acc1, i1);
    }
    while (lo) { int i0 = __ffs(lo) - 1;  lo &= lo - 1; STEP(acc0, i0); }
    while (hi) { int i1 = __ffs(hi) + 31; hi &= hi - 1; STEP(acc1, i1); }
#undef STEP

    out[base + r * 64 + o] = acc0 + acc1;
}

// ---------------------------------------------------------------------------
extern "C" void kernel_launch(void* const* d_in, const int* in_sizes, int n_in,
                              void* d_out, int out_size)
{
    const float* x   = (const float*)d_in[0];
    const float* rg  = (const float*)d_in[1];
    const float* w   = (const float*)d_in[2];
    const float* br  = (const float*)d_in[3];
    const float* cf  = (const float*)d_in[4];
    const float* mu  = (const float*)d_in[5];
    const float* sg  = (const float*)d_in[6];
    float* out = (float*)d_out;

    setup_kernel<<<(NIO * NIO + 255) / 256, 256>>>(rg, w, br, cf, mu, sg);
    main_kernel<<<NB / TILE_B, THREADS>>>(x, out);
}

// round 6
// speedup vs baseline: 1.6628x; 1.0557x over previous
#include <cuda_runtime.h>

#define TILE_B   4
#define THREADS  256
#define NB       8192
#define NIO      64

// Precomputed per-(o,i) coefficient tables, laid out [i][o] for coalesced
// per-o lane reads.  A = {c1', b2', b3', b4}, B = {c5..c8} (gamma/64 folded).
__device__ float4 g_tabA[NIO * NIO];
__device__ float4 g_tabB[NIO * NIO];

__device__ __forceinline__ float ex2f_(float x) {
    float y; asm("ex2.approx.ftz.f32 %0, %1;" : "=f"(y) : "f"(x)); return y;
}
__device__ __forceinline__ float lg2f_(float x) {
    float y; asm("lg2.approx.ftz.f32 %0, %1;" : "=f"(y) : "f"(x)); return y;
}

// ---------------------------------------------------------------------------
// Setup: evaluate the 8 cubic splines at w_norm for every (o,i) pair and fold
// all constant factors so the main loop is pure EX2/LG2 + FFMA.
// ---------------------------------------------------------------------------
__global__ void setup_kernel(const float* __restrict__ raw_gamma,
                             const float* __restrict__ w,
                             const float* __restrict__ breaks,
                             const float* __restrict__ coefs,
                             const float* __restrict__ mu_p,
                             const float* __restrict__ sig_p)
{
    int tid = blockIdx.x * blockDim.x + threadIdx.x;
    if (tid >= NIO * NIO) return;
    int o = tid >> 6;
    int i = tid & 63;

    float mu  = *mu_p;
    float sig = *sig_p;
    float wv  = w[tid];                       // w[o][i]
    float wc  = fminf(fmaxf(wv, -5.5f), 37.9f);
    float wn  = (wc - mu) / sig;

    float b[8];
#pragma unroll
    for (int s = 0; s < 8; s++) {
        const float* br = breaks + s * 20;
        float blo = br[0];
        float bhi = br[19] - 1e-6f;
        float wl  = fminf(fmaxf(wn, blo), bhi);
        int cnt = 0;
#pragma unroll
        for (int k = 0; k < 20; k++) cnt += (br[k] < wl) ? 1 : 0;
        int idx = cnt - 1;
        idx = max(idx, 0);
        idx = min(idx, 18);
        const float* a = coefs + (s * 19 + idx) * 4;
        float t = wl - br[idx];
        b[s] = ((a[0] * t + a[1]) * t + a[2]) * t + a[3];
    }

    float rg = raw_gamma[tid];
    float g  = (rg > 20.f) ? rg : log1pf(expf(rg));   // softplus
    float scale = g * (1.0f / 64.0f);

    const float LN2   = 0.6931471805599453f;
    const float LOG2E = 1.4426950408889634f;

    float4 A, Bq;
    A.x = b[0] * scale * LN2;   // c1'
    A.y = b[1] * LN2;           // b2'
    A.z = b[2] * LOG2E;         // b3'
    A.w = b[3];                 // b4
    Bq.x = b[4] * scale;
    Bq.y = b[5] * scale;
    Bq.z = b[6] * scale;
    Bq.w = b[7] * scale;

    int p = i * NIO + o;        // [i][o] layout
    g_tabA[p] = A;
    g_tabB[p] = Bq;
}

// ---------------------------------------------------------------------------
// Main kernel.  Block = 256 threads = 8 warps, TILE_B=4 rows, grid=2048.
// Warp wp -> row (wp>>1), o-half (wp&1).  Two independent MUFU chains drain
// the lo/hi activity masks together; the balanced portion is SOFTWARE
// PIPELINED: iteration k issues the loads for step k+1 before running the
// MUFU chains for step k, hiding LDG latency + branch overhead inside the
// ~110-cycle MUFU chain.  All control flow is warp-uniform (ballot masks).
// ---------------------------------------------------------------------------
__global__ __launch_bounds__(THREADS)
void main_kernel(const float* __restrict__ x, float* __restrict__ out)
{
    __shared__ float xs[TILE_B * 64];

    const int tid   = threadIdx.x;
    const long base = (long)blockIdx.x * (TILE_B * 64);

    // Phase 1: load x tile + relu (one element per thread, coalesced)
    xs[tid] = fmaxf(x[base + tid], 0.f);
    __syncthreads();

    const int lane = tid & 31;
    const int wp   = tid >> 5;
    const int r    = wp >> 1;
    const int o    = lane + (wp & 1) * 32;

    const float* xrow = xs + r * 64;
    float v0 = xrow[lane];
    float v1 = xrow[lane + 32];
    unsigned lo = __ballot_sync(0xffffffffu, v0 > 0.f);
    unsigned hi = __ballot_sync(0xffffffffu, v1 > 0.f);

    const float4* tA = g_tabA + o;
    const float4* tB = g_tabB + o;

    float acc0 = 0.f, acc1 = 0.f;

    // COMPUTE on already-loaded operands (5 MUFU + FFMA, no memory)
#define CHAIN(ACC, XV, A, Bq)                                             \
    {                                                                     \
        float e  = ex2f_((A).z * (XV)) - 1.f;                             \
        float p  = ex2f_((A).w * lg2f_(e));                               \
        float l1 = lg2f_(1.f + p);                                        \
        float l2 = lg2f_(fmaf((A).y, l1, 1.f));                           \
        ACC = fmaf((A).x, l2, ACC);                                       \
        float x2 = (XV) * (XV);                                           \
        float pA = fmaf((Bq).z, x2, (Bq).x);                              \
        float pB = fmaf((Bq).w, x2, (Bq).y);                              \
        ACC = fmaf(fmaf(pB, (XV), pA), (XV), ACC);                        \
    }

    int nb = min(__popc(lo), __popc(hi));

    if (nb > 0) {
        // Prologue: fetch step 0 for both chains
        int i0 = __ffs(lo) - 1;  lo &= lo - 1;
        int i1 = __ffs(hi) + 31; hi &= hi - 1;
        float  xv0 = xrow[i0];
        float  xv1 = xrow[i1];
        float4 A0  = __ldg(tA + i0 * NIO);
        float4 B0  = __ldg(tB + i0 * NIO);
        float4 A1  = __ldg(tA + i1 * NIO);
        float4 B1  = __ldg(tB + i1 * NIO);

        for (int k = 1; k < nb; k++) {
            // FETCH next step (independent of the chains below)
            int j0 = __ffs(lo) - 1;  lo &= lo - 1;
            int j1 = __ffs(hi) + 31; hi &= hi - 1;
            float  nxv0 = xrow[j0];
            float  nxv1 = xrow[j1];
            float4 nA0  = __ldg(tA + j0 * NIO);
            float4 nB0  = __ldg(tB + j0 * NIO);
            float4 nA1  = __ldg(tA + j1 * NIO);
            float4 nB1  = __ldg(tB + j1 * NIO);

            // COMPUTE current step (2 independent MUFU chains)
            CHAIN(acc0, xv0, A0, B0);
            CHAIN(acc1, xv1, A1, B1);

            // rotate
            xv0 = nxv0; A0 = nA0; B0 = nB0;
            xv1 = nxv1; A1 = nA1; B1 = nB1;
        }
        // Epilogue
        CHAIN(acc0, xv0, A0, B0);
        CHAIN(acc1, xv1, A1, B1);
    }

    // Remainder drains (one mask is already empty; counts are small)
    while (lo) {
        int i0 = __ffs(lo) - 1; lo &= lo - 1;
        float  xv = xrow[i0];
        float4 A  = __ldg(tA + i0 * NIO);
        float4 Bq = __ldg(tB + i0 * NIO);
        CHAIN(acc0, xv, A, Bq);
    }
    while (hi) {
        int i1 = __ffs(hi) + 31; hi &= hi - 1;
        float  xv = xrow[i1];
        float4 A  = __ldg(tA + i1 * NIO);
        float4 Bq = __ldg(tB + i1 * NIO);
        CHAIN(acc1, xv, A, Bq);
    }
#undef CHAIN

    out[base + r * 64 + o] = acc0 + acc1;
}

// ---------------------------------------------------------------------------
extern "C" void kernel_launch(void* const* d_in, const int* in_sizes, int n_in,
                              void* d_out, int out_size)
{
    const float* x   = (const float*)d_in[0];
    const float* rg  = (const float*)d_in[1];
    const float* w   = (const float*)d_in[2];
    const float* br  = (const float*)d_in[3];
    const float* cf  = (const float*)d_in[4];
    const float* mu  = (const float*)d_in[5];
    const float* sg  = (const float*)d_in[6];
    float* out = (float*)d_out;

    setup_kernel<<<(NIO * NIO + 255) / 256, 256>>>(rg, w, br, cf, mu, sg);
    main_kernel<<<NB / TILE_B, THREADS>>>(x, out);
}